// round 16
// baseline (speedup 1.0000x reference)
#include <cuda_runtime.h>
#include <stdint.h>

#define NUM_CLASSES 100000
#define EMBED_DIM   512
#define BATCH       16384
#define NBUILD      64                    // build blocks inside K1
#define NCOPYB      6144                  // flat copy blocks in K1
#define TOTF        (NUM_CLASSES * (size_t)EMBED_DIM)   // 51,200,000 floats
#define NGROUPS     ((TOTF - 4) / 4)      // 12,799,999 aligned float4 groups

// Self-cleaning scratch (zero-initialized; every call restores zeros).
__device__ int g_head[NUM_CLASSES];      // idx+1 of chain head, 0 = empty
__device__ int g_next[BATCH];            // idx+1 of next in chain, 0 = end

// ---------------------------------------------------------------------------
// K1: build blocks [0,NBUILD) build chains + zero loss; the rest flat-copy
// ALL of center_var into out+1 (branch-free, globally aligned stores).
// ---------------------------------------------------------------------------
__global__ __launch_bounds__(256)
void copy_build_kernel(const int* __restrict__ labels,
                       const float* __restrict__ center_var,
                       float* __restrict__ out) {
    const int t = threadIdx.x;

    if (blockIdx.x < NBUILD) {
        // ----- build: 16384 items over 64 blocks x 256 threads -------------
        int i = blockIdx.x * 256 + t;
        if (i == 0) {
            out[0] = 0.0f;                          // loss slot
            // edge floats of the copy (head 3 + tail 1)
            const float4 h = *reinterpret_cast<const float4*>(center_var);
            out[1] = h.x; out[2] = h.y; out[3] = h.z;
            out[TOTF] = center_var[TOTF - 1];
        }
        if (i < BATCH) {
            int l = labels[i];
            g_next[i] = atomicExch(&g_head[l], i + 1);
        }
        return;
    }

    // ----- flat copy: group g covers src floats [4g+3, 4g+6] ---------------
    // dst = out+1+3+4g is 16B-aligned (out is 16B-aligned).
    const float4* s4 = reinterpret_cast<const float4*>(center_var);
    float* outc = out + 1;

    size_t g = (size_t)(blockIdx.x - NBUILD) * 256 + t;
    const size_t stride = (size_t)NCOPYB * 256;

    #pragma unroll 4
    for (; g < NGROUPS; g += stride) {
        float4 a = s4[g];
        float4 b = s4[g + 1];                       // L1-hit overlap
        *reinterpret_cast<float4*>(outc + 3 + 4 * g) =
            make_float4(a.w, b.x, b.y, b.z);
    }
}

// ---------------------------------------------------------------------------
// K2: update touched rows (overwrite copied values) + loss.
// One block per batch item; only chain heads do work, BUT all independent
// loads are hoisted above the head check so the block's memory is in flight
// from cycle 0 (feature row + g_next depend on nothing; head + center row
// depend only on labels[i]).
// ---------------------------------------------------------------------------
__global__ __launch_bounds__(128)
void update_kernel(const float* __restrict__ features,
                   const int* __restrict__ labels,
                   const float* __restrict__ center_var,
                   float* __restrict__ out) {
    const int t = threadIdx.x;
    const int i = blockIdx.x;

    // --- independent loads, all issued before any branch -------------------
    const float4* frow =
        reinterpret_cast<const float4*>(features + (size_t)i * EMBED_DIM);
    float4 f = frow[t];                  // own feature row: zero deps
    const int nxt = g_next[i];           // zero deps
    const int l = labels[i];             // one dep level:
    const int h = g_head[l];             //   head  (after labels)
    const float4* crow =
        reinterpret_cast<const float4*>(center_var + (size_t)l * EMBED_DIM);
    float4 c = crow[t];                  //   center row (after labels)

    if (h != i + 1) return;              // not chain head: discard (rare)

    float dx = f.x - c.x, dy = f.y - c.y, dz = f.z - c.z, dw = f.w - c.w;
    float lossp = dx * dx + dy * dy + dz * dz + dw * dw;
    float4 fs = f;
    int n = 1;

    // walk remaining duplicates (present for ~8% of heads)
    for (int j = nxt; j != 0; j = g_next[j - 1]) {
        const float4* fr =
            reinterpret_cast<const float4*>(features + (size_t)(j - 1) * EMBED_DIM);
        float4 ff = fr[t];
        float ex = ff.x - c.x, ey = ff.y - c.y, ez = ff.z - c.z, ew = ff.w - c.w;
        lossp += ex * ex + ey * ey + ez * ez + ew * ew;
        fs.x += ff.x; fs.y += ff.y; fs.z += ff.z; fs.w += ff.w;
        n++;
    }

    // new = c + 0.05 * (sum_f - n*c)
    const float a = 0.05f;
    const float fn = (float)n;
    __shared__ float srow[EMBED_DIM];
    srow[4 * t + 0] = c.x + a * (fs.x - fn * c.x);
    srow[4 * t + 1] = c.y + a * (fs.y - fn * c.y);
    srow[4 * t + 2] = c.z + a * (fs.z - fn * c.z);
    srow[4 * t + 3] = c.w + a * (fs.w - fn * c.w);
    __syncthreads();

    float* orow = out + 1 + (size_t)l * EMBED_DIM;
    if (t < 127) {
        *reinterpret_cast<float4*>(orow + 3 + 4 * t) =
            make_float4(srow[4 * t + 3], srow[4 * t + 4],
                        srow[4 * t + 5], srow[4 * t + 6]);
    } else {
        orow[0] = srow[0]; orow[1] = srow[1]; orow[2] = srow[2];
        orow[511] = srow[511];
    }

    // block-reduce loss, single atomic per chain; self-clean head
    #pragma unroll
    for (int off = 16; off > 0; off >>= 1)
        lossp += __shfl_down_sync(0xFFFFFFFFu, lossp, off);
    __shared__ float ws[4];
    if ((t & 31) == 0) ws[t >> 5] = lossp;
    __syncthreads();
    if (t == 0) {
        const float inv_n = 1.0f / ((float)BATCH * (float)EMBED_DIM);
        atomicAdd(out, (ws[0] + ws[1] + ws[2] + ws[3]) * inv_n);
        g_head[l] = 0;                   // self-clean for next call
    }
}

// ---------------------------------------------------------------------------
// Launch
// ---------------------------------------------------------------------------
extern "C" void kernel_launch(void* const* d_in, const int* in_sizes, int n_in,
                              void* d_out, int out_size) {
    const float* features   = (const float*)d_in[0];
    const int*   labels     = (const int*)d_in[1];
    const float* center_var = (const float*)d_in[2];
    float* out = (float*)d_out;

    copy_build_kernel<<<NBUILD + NCOPYB, 256>>>(labels, center_var, out);
    update_kernel<<<BATCH, 128>>>(features, labels, center_var, out);
}

// round 17
// speedup vs baseline: 1.0025x; 1.0025x over previous
#include <cuda_runtime.h>
#include <stdint.h>

#define NUM_CLASSES 100000
#define EMBED_DIM   512
#define BATCH       16384
#define NBUILD      64                    // build blocks inside K1
#define NCOPYB      6144                  // flat copy blocks in K1
#define TOTF        (NUM_CLASSES * (size_t)EMBED_DIM)   // 51,200,000 floats
#define NGROUPS     ((TOTF - 4) / 4)      // 12,799,999 aligned float4 groups

// Self-cleaning scratch (zero-initialized; every call restores zeros).
__device__ int g_head[NUM_CLASSES];      // idx+1 of chain head, 0 = empty
__device__ int g_next[BATCH];            // idx+1 of next in chain, 0 = end

// ---------------------------------------------------------------------------
// K1: build blocks [0,NBUILD) build chains + zero loss; the rest flat-copy
// ALL of center_var into out+1 (branch-free, globally aligned stores).
// ---------------------------------------------------------------------------
__global__ __launch_bounds__(256)
void copy_build_kernel(const int* __restrict__ labels,
                       const float* __restrict__ center_var,
                       float* __restrict__ out) {
    const int t = threadIdx.x;

    if (blockIdx.x < NBUILD) {
        int i = blockIdx.x * 256 + t;
        if (i == 0) {
            out[0] = 0.0f;                          // loss slot
            const float4 h = *reinterpret_cast<const float4*>(center_var);
            out[1] = h.x; out[2] = h.y; out[3] = h.z;
            out[TOTF] = center_var[TOTF - 1];
        }
        if (i < BATCH) {
            int l = labels[i];
            g_next[i] = atomicExch(&g_head[l], i + 1);
        }
        return;
    }

    // flat copy: group g covers src floats [4g+3, 4g+6];
    // dst = out+1+3+4g is 16B-aligned.
    const float4* s4 = reinterpret_cast<const float4*>(center_var);
    float* outc = out + 1;

    size_t g = (size_t)(blockIdx.x - NBUILD) * 256 + t;
    const size_t stride = (size_t)NCOPYB * 256;

    #pragma unroll 4
    for (; g < NGROUPS; g += stride) {
        float4 a = s4[g];
        float4 b = s4[g + 1];                       // L1-hit overlap
        *reinterpret_cast<float4*>(outc + 3 + 4 * g) =
            make_float4(a.w, b.x, b.y, b.z);
    }
}

// ---------------------------------------------------------------------------
// K2: warp-per-item update. Each lane owns 4 float4 chunks (MLP=4). 8 warps
// per block, one loss atomic per block. Plain stores overwrite copied rows
// (kernel boundary orders against K1).
// ---------------------------------------------------------------------------
__global__ __launch_bounds__(256)
void update_kernel(const float* __restrict__ features,
                   const int* __restrict__ labels,
                   const float* __restrict__ center_var,
                   float* __restrict__ out) {
    const int t    = threadIdx.x;
    const int lane = t & 31;
    const int w    = t >> 5;
    const int i    = blockIdx.x * 8 + w;            // batch item for this warp

    __shared__ float srow[8][EMBED_DIM];            // per-warp staging
    __shared__ float ws[8];

    // --- loads, all in flight before the head check ------------------------
    const float4* frow =
        reinterpret_cast<const float4*>(features + (size_t)i * EMBED_DIM);
    float4 f0 = frow[lane], f1 = frow[lane + 32],
           f2 = frow[lane + 64], f3 = frow[lane + 96];
    const int nxt = g_next[i];
    const int l   = labels[i];
    const int h   = g_head[l];
    const float4* crow =
        reinterpret_cast<const float4*>(center_var + (size_t)l * EMBED_DIM);
    float4 c0 = crow[lane], c1 = crow[lane + 32],
           c2 = crow[lane + 64], c3 = crow[lane + 96];

    const bool ishead = (h == i + 1);               // warp-uniform
    float lossp = 0.0f;

    if (ishead) {
        float4 s0 = f0, s1 = f1, s2 = f2, s3 = f3;
        {
            float dx, dy, dz, dw;
            dx = f0.x-c0.x; dy = f0.y-c0.y; dz = f0.z-c0.z; dw = f0.w-c0.w;
            lossp += dx*dx + dy*dy + dz*dz + dw*dw;
            dx = f1.x-c1.x; dy = f1.y-c1.y; dz = f1.z-c1.z; dw = f1.w-c1.w;
            lossp += dx*dx + dy*dy + dz*dz + dw*dw;
            dx = f2.x-c2.x; dy = f2.y-c2.y; dz = f2.z-c2.z; dw = f2.w-c2.w;
            lossp += dx*dx + dy*dy + dz*dz + dw*dw;
            dx = f3.x-c3.x; dy = f3.y-c3.y; dz = f3.z-c3.z; dw = f3.w-c3.w;
            lossp += dx*dx + dy*dy + dz*dz + dw*dw;
        }
        int n = 1;

        // duplicate chain (~8% of heads)
        for (int j = nxt; j != 0; j = g_next[j - 1]) {
            const float4* fr =
                reinterpret_cast<const float4*>(features + (size_t)(j - 1) * EMBED_DIM);
            float4 g0 = fr[lane], g1 = fr[lane + 32],
                   g2 = fr[lane + 64], g3 = fr[lane + 96];
            float dx, dy, dz, dw;
            dx = g0.x-c0.x; dy = g0.y-c0.y; dz = g0.z-c0.z; dw = g0.w-c0.w;
            lossp += dx*dx + dy*dy + dz*dz + dw*dw;
            dx = g1.x-c1.x; dy = g1.y-c1.y; dz = g1.z-c1.z; dw = g1.w-c1.w;
            lossp += dx*dx + dy*dy + dz*dz + dw*dw;
            dx = g2.x-c2.x; dy = g2.y-c2.y; dz = g2.z-c2.z; dw = g2.w-c2.w;
            lossp += dx*dx + dy*dy + dz*dz + dw*dw;
            dx = g3.x-c3.x; dy = g3.y-c3.y; dz = g3.z-c3.z; dw = g3.w-c3.w;
            lossp += dx*dx + dy*dy + dz*dz + dw*dw;
            s0.x += g0.x; s0.y += g0.y; s0.z += g0.z; s0.w += g0.w;
            s1.x += g1.x; s1.y += g1.y; s1.z += g1.z; s1.w += g1.w;
            s2.x += g2.x; s2.y += g2.y; s2.z += g2.z; s2.w += g2.w;
            s3.x += g3.x; s3.y += g3.y; s3.z += g3.z; s3.w += g3.w;
            n++;
        }

        // new = c + 0.05 * (sum_f - n*c) -> stage in smem
        const float a = 0.05f, fn = (float)n;
        float* sr = srow[w];
        int p = 4 * lane;
        sr[p+0]   = c0.x + a*(s0.x - fn*c0.x);
        sr[p+1]   = c0.y + a*(s0.y - fn*c0.y);
        sr[p+2]   = c0.z + a*(s0.z - fn*c0.z);
        sr[p+3]   = c0.w + a*(s0.w - fn*c0.w);
        sr[p+128] = c1.x + a*(s1.x - fn*c1.x);
        sr[p+129] = c1.y + a*(s1.y - fn*c1.y);
        sr[p+130] = c1.z + a*(s1.z - fn*c1.z);
        sr[p+131] = c1.w + a*(s1.w - fn*c1.w);
        sr[p+256] = c2.x + a*(s2.x - fn*c2.x);
        sr[p+257] = c2.y + a*(s2.y - fn*c2.y);
        sr[p+258] = c2.z + a*(s2.z - fn*c2.z);
        sr[p+259] = c2.w + a*(s2.w - fn*c2.w);
        sr[p+384] = c3.x + a*(s3.x - fn*c3.x);
        sr[p+385] = c3.y + a*(s3.y - fn*c3.y);
        sr[p+386] = c3.z + a*(s3.z - fn*c3.z);
        sr[p+387] = c3.w + a*(s3.w - fn*c3.w);
        __syncwarp();

        // store: 127 aligned float4 groups + 4 edge floats
        float* orow = out + 1 + (size_t)l * EMBED_DIM;
        #pragma unroll
        for (int k = 0; k < 4; k++) {
            int g = lane + 32 * k;
            if (g < 127) {
                *reinterpret_cast<float4*>(orow + 3 + 4 * g) =
                    make_float4(sr[4*g+3], sr[4*g+4], sr[4*g+5], sr[4*g+6]);
            }
        }
        if (lane == 0) {
            orow[0] = sr[0]; orow[1] = sr[1]; orow[2] = sr[2];
            orow[511] = sr[511];
            g_head[l] = 0;               // self-clean for next call
        }
    }

    // warp loss reduce (all warps participate; non-heads contribute 0)
    #pragma unroll
    for (int off = 16; off > 0; off >>= 1)
        lossp += __shfl_down_sync(0xFFFFFFFFu, lossp, off);
    if (lane == 0) ws[w] = lossp;
    __syncthreads();
    if (t == 0) {
        float blk = ws[0]+ws[1]+ws[2]+ws[3]+ws[4]+ws[5]+ws[6]+ws[7];
        const float inv_n = 1.0f / ((float)BATCH * (float)EMBED_DIM);
        atomicAdd(out, blk * inv_n);
    }
}

// ---------------------------------------------------------------------------
// Launch
// ---------------------------------------------------------------------------
extern "C" void kernel_launch(void* const* d_in, const int* in_sizes, int n_in,
                              void* d_out, int out_size) {
    const float* features   = (const float*)d_in[0];
    const int*   labels     = (const int*)d_in[1];
    const float* center_var = (const float*)d_in[2];
    float* out = (float*)d_out;

    copy_build_kernel<<<NBUILD + NCOPYB, 256>>>(labels, center_var, out);
    update_kernel<<<BATCH / 8, 256>>>(features, labels, center_var, out);
}